// round 2
// baseline (speedup 1.0000x reference)
#include <cuda_runtime.h>

// BillehColumn GLIF3 simulation, forward only.
// Round 2: persistent simulation kernel. One thread per neuron, all neuron
// state in registers across all 50 timesteps; software grid barrier between
// steps (148 blocks, all resident in wave 1). Cross-block rec buffers are
// accessed L2-coherently (__ldcg / __stcg / atomics).

#define Nn 100000
#define Rr 4
#define Ee 2000000
#define Tt 50
#define NRr (Nn * Rr)
#define SCAN_BLOCKS 98   // ceil(100000/1024)
#define GRID 148
#define TPB 1024

__device__ float g_rec[2][NRr];
__device__ int   g_cnt[Nn];
__device__ int   g_offs[Nn];
__device__ int   g_cursor[Nn];
__device__ int   g_syn_tgt[Ee];
__device__ float g_syn_w[Ee];
__device__ int   g_bsum[128];
__device__ int   g_bar;

// ---------------------------------------------------------------------------
// Init: zero rec buffers, counts, barrier counter.
__global__ void k_init() {
    int i = blockIdx.x * blockDim.x + threadIdx.x;
    if (i < NRr) {
        g_rec[0][i] = 0.f;
        g_rec[1][i] = 0.f;
    }
    if (i < Nn) g_cnt[i] = 0;
    if (i == 0) g_bar = 0;
}

// Histogram of synapse pre-neuron ids.
__global__ void k_hist(const int* __restrict__ pre) {
    int e = blockIdx.x * blockDim.x + threadIdx.x;
    if (e < Ee) atomicAdd(&g_cnt[pre[e]], 1);
}

// Block-level exclusive scan of g_cnt -> g_offs, block sums -> g_bsum.
__global__ void k_scan1() {
    __shared__ int sh[1024];
    int tid = threadIdx.x;
    int idx = blockIdx.x * 1024 + tid;
    int v = (idx < Nn) ? g_cnt[idx] : 0;
    sh[tid] = v;
    __syncthreads();
#pragma unroll
    for (int off = 1; off < 1024; off <<= 1) {
        int t = (tid >= off) ? sh[tid - off] : 0;
        __syncthreads();
        sh[tid] += t;
        __syncthreads();
    }
    int inc = sh[tid];
    if (idx < Nn) g_offs[idx] = inc - v;
    if (tid == 1023) g_bsum[blockIdx.x] = inc;
}

// Exclusive scan of block sums (SCAN_BLOCKS <= 128), single block of 128.
__global__ void k_scan2() {
    __shared__ int sh[128];
    int tid = threadIdx.x;
    int v = (tid < SCAN_BLOCKS) ? g_bsum[tid] : 0;
    sh[tid] = v;
    __syncthreads();
#pragma unroll
    for (int off = 1; off < 128; off <<= 1) {
        int t = (tid >= off) ? sh[tid - off] : 0;
        __syncthreads();
        sh[tid] += t;
        __syncthreads();
    }
    g_bsum[tid] = sh[tid] - v;  // exclusive
}

// Add block bases; init scatter cursors.
__global__ void k_scan3() {
    int i = blockIdx.x * blockDim.x + threadIdx.x;
    if (i < Nn) {
        int o = g_offs[i] + g_bsum[i >> 10];
        g_offs[i] = o;
        g_cursor[i] = o;
    }
}

// Fill CSR: synapses grouped by pre neuron.
__global__ void k_fill(const int* __restrict__ pre,
                       const int* __restrict__ post,
                       const int* __restrict__ rcp,
                       const float* __restrict__ w) {
    int e = blockIdx.x * blockDim.x + threadIdx.x;
    if (e < Ee) {
        int p = pre[e];
        int pos = atomicAdd(&g_cursor[p], 1);
        g_syn_tgt[pos] = post[e] * Rr + rcp[e];
        g_syn_w[pos] = w[e];
    }
}

// ---------------------------------------------------------------------------
// Persistent simulation: all 50 timesteps in one kernel. State in registers.
__global__ void __launch_bounds__(TPB, 1) k_sim(
    const float* __restrict__ x_ext,
    float* __restrict__ out,
    const float* __restrict__ v0,
    const float* __restrict__ vth_,
    const float* __restrict__ vreset_,
    const float* __restrict__ tref_,
    const float* __restrict__ decay_,
    const float* __restrict__ cf_,
    const float* __restrict__ el_,
    const float* __restrict__ amps_,
    const float* __restrict__ ascd_,
    const float* __restrict__ syn_decay,
    const float* __restrict__ psc_init)
{
    const int n = blockIdx.x * TPB + threadIdx.x;
    const bool act = (n < Nn);

    const float4 sd = *(const float4*)syn_decay;
    const float4 pi = *(const float4*)psc_init;

    // Register-resident state.
    float v = 0.f, r = 0.f, z = 0.f;
    float2 a = make_float2(0.f, 0.f);
    float4 psc = make_float4(0.f, 0.f, 0.f, 0.f);
    float4 pr  = make_float4(0.f, 0.f, 0.f, 0.f);
    // Register-resident params.
    float vth = 1.f, vrs = 0.f, trf = 0.f, dec = 0.f, cf = 0.f, el = 0.f;
    float2 am = make_float2(0.f, 0.f), ad = make_float2(0.f, 0.f);
    int so = 0, sc = 0;

    if (act) {
        v   = v0[n];
        vth = vth_[n];
        vrs = vreset_[n];
        trf = tref_[n];
        dec = decay_[n];
        cf  = cf_[n];
        el  = el_[n];
        am  = *(const float2*)(&amps_[2 * n]);
        ad  = *(const float2*)(&ascd_[2 * n]);
        so  = g_offs[n];
        sc  = g_cnt[n];
    }

    for (int t = 0; t < Tt; t++) {
        float* rec_cur = g_rec[t & 1];
        float* rec_nxt = g_rec[(t + 1) & 1];

        if (act) {
            // L2-coherent read-and-zero of this neuron's rec slots.
            float4 rec = __ldcg((const float4*)(rec_cur + 4 * n));
            __stcg((float4*)(rec_cur + 4 * n), make_float4(0.f, 0.f, 0.f, 0.f));

            float4 x = __ldg((const float4*)x_ext + (size_t)t * Nn + n);

            float in0 = rec.x + x.x;
            float in1 = rec.y + x.y;
            float in2 = rec.z + x.z;
            float in3 = rec.w + x.w;

            float4 npr, npsc;
            npr.x = pr.x * sd.x + in0 * pi.x;
            npr.y = pr.y * sd.y + in1 * pi.y;
            npr.z = pr.z * sd.z + in2 * pi.z;
            npr.w = pr.w * sd.w + in3 * pi.w;
            npsc.x = psc.x * sd.x + sd.x * pr.x;
            npsc.y = psc.y * sd.y + sd.y * pr.y;
            npsc.z = psc.z * sd.z + sd.z * pr.z;
            npsc.w = psc.w * sd.w + sd.w * pr.w;
            psc = npsc;
            pr = npr;

            float psum = ((npsc.x + npsc.y) + npsc.z) + npsc.w;
            float input_current = psum + (a.x + a.y);   // uses OLD asc

            a.x = ad.x * a.x + z * am.x;
            a.y = ad.y * a.y + z * am.y;

            float nv = dec * v + cf * (input_current + el) + z * (vrs - vth);
            float vsc = (nv - vth) / vth;

            float zn = (vsc > 0.f) ? 1.f : 0.f;
            if (r > 0.f) zn = 0.f;
            float rn = fmaxf(r - 1.f + zn * trf, 0.f);

            v = nv;
            r = rn;
            z = zn;
            out[(size_t)t * Nn + n] = zn;

            // Push this neuron's spike into next step's rec buffer.
            if (zn != 0.f) {
                int s = so;
                int e = so + sc;
                for (; s < e; s++) {
                    atomicAdd(&rec_nxt[g_syn_tgt[s]], g_syn_w[s]);
                }
            }
        }

        // Grid barrier between steps (skip after final step).
        if (t + 1 < Tt) {
            __syncthreads();
            if (threadIdx.x == 0) {
                __threadfence();
                atomicAdd(&g_bar, 1);
                const int target = GRID * (t + 1);
                while (*((volatile int*)&g_bar) < target) { }
            }
            __syncthreads();
        }
    }
}

// ---------------------------------------------------------------------------
extern "C" void kernel_launch(void* const* d_in, const int* in_sizes, int n_in,
                              void* d_out, int out_size) {
    const float* w_rec     = (const float*)d_in[0];
    const float* x_ext     = (const float*)d_in[1];
    const float* v0        = (const float*)d_in[2];
    const float* vth       = (const float*)d_in[3];
    const float* vreset    = (const float*)d_in[4];
    const float* tref      = (const float*)d_in[5];
    const float* decay     = (const float*)d_in[6];
    const float* cf        = (const float*)d_in[7];
    const float* el        = (const float*)d_in[8];
    const float* amps      = (const float*)d_in[9];
    const float* ascd      = (const float*)d_in[10];
    const float* syn_decay = (const float*)d_in[11];
    const float* psc_init  = (const float*)d_in[12];
    const int*   pre       = (const int*)d_in[13];
    const int*   post      = (const int*)d_in[14];
    const int*   rcp       = (const int*)d_in[15];
    float* out = (float*)d_out;

    k_init<<<(NRr + 255) / 256, 256>>>();
    k_hist<<<(Ee + 255) / 256, 256>>>(pre);
    k_scan1<<<SCAN_BLOCKS, 1024>>>();
    k_scan2<<<1, 128>>>();
    k_scan3<<<(Nn + 255) / 256, 256>>>();
    k_fill<<<(Ee + 255) / 256, 256>>>(pre, post, rcp, w_rec);

    k_sim<<<GRID, TPB>>>(x_ext, out, v0, vth, vreset, tref, decay, cf, el,
                         amps, ascd, syn_decay, psc_init);
}

// round 3
// speedup vs baseline: 1.1225x; 1.1225x over previous
#include <cuda_runtime.h>

// BillehColumn GLIF3 simulation, forward only.
// Round 3: slim preprocessing. Fixed-stride synapse buckets (no hist/scan),
// single fused init+param-pack kernel, vectorized fill, 50 small step kernels
// (one per timestep; kernel boundary = grid sync).

#define Nn 100000
#define Rr 4
#define Ee 2000000
#define Tt 50
#define NRr (Nn * Rr)
#define SS 64                 // synapse slots per pre-neuron
#define OVF_CAP 4096

// Contiguous zero-initialized state blob (floats):
//   [0,        800000)  rec[2][NR]
//   [800000,  1200000)  psc[NR]
//   [1200000, 1600000)  psc_rise[NR]
//   [1600000, 1800000)  asc[2N]
//   [1800000, 1900000)  cnt[N]      (as int)
//   [1900000, 1900004)  ovf_cnt + pad (as int)
#define BLOB_FLOATS 1900004
#define OFF_REC 0
#define OFF_PSC 800000
#define OFF_PR  1200000
#define OFF_ASC 1600000
#define OFF_CNT 1800000
#define OFF_OVF 1900000

__device__ float  g_blob[BLOB_FLOATS];
__device__ float4 g_pA[Nn];        // vth, (vreset - vth), tref, decay
__device__ float4 g_pB[Nn];        // cf, el, amp0, amp1
__device__ float2 g_pC[Nn];        // ascd0, ascd1
__device__ float4 g_state[Nn];     // v, r, z, unused
__device__ int    g_syn_tgt[Nn * SS];
__device__ float  g_syn_w[Nn * SS];
__device__ int    g_ovf_pre[OVF_CAP];
__device__ int    g_ovf_tgt[OVF_CAP];
__device__ float  g_ovf_w[OVF_CAP];

// ---------------------------------------------------------------------------
// Fused init: zero the blob (float4 grid-stride), pack params, init state.
__global__ void k_prep(const float* __restrict__ v0,
                       const float* __restrict__ vth,
                       const float* __restrict__ vreset,
                       const float* __restrict__ tref,
                       const float* __restrict__ decay,
                       const float* __restrict__ cf,
                       const float* __restrict__ el,
                       const float* __restrict__ amps,
                       const float* __restrict__ ascd) {
    int i = blockIdx.x * blockDim.x + threadIdx.x;
    const int nf4 = BLOB_FLOATS / 4;
    float4* blob4 = (float4*)g_blob;
    for (int j = i; j < nf4; j += gridDim.x * blockDim.x) {
        blob4[j] = make_float4(0.f, 0.f, 0.f, 0.f);
    }
    if (i < Nn) {
        float t = vth[i];
        g_pA[i] = make_float4(t, vreset[i] - t, tref[i], decay[i]);
        float2 am = *(const float2*)(&amps[2 * i]);
        g_pB[i] = make_float4(cf[i], el[i], am.x, am.y);
        g_pC[i] = *(const float2*)(&ascd[2 * i]);
        g_state[i] = make_float4(v0[i], 0.f, 0.f, 0.f);
    }
}

// ---------------------------------------------------------------------------
// Single-pass synapse bucketing: slot = pre*SS + running count.
// 4 synapses per thread (int4/float4 loads).
__global__ void k_fill(const int* __restrict__ pre,
                       const int* __restrict__ post,
                       const int* __restrict__ rcp,
                       const float* __restrict__ w) {
    int i = blockIdx.x * blockDim.x + threadIdx.x;   // quad index
    if (i >= Ee / 4) return;
    int4 p4 = ((const int4*)pre)[i];
    int4 q4 = ((const int4*)post)[i];
    int4 r4 = ((const int4*)rcp)[i];
    float4 w4 = ((const float4*)w)[i];

    int* cnt = (int*)(g_blob + OFF_CNT);
    int* ovf_cnt = (int*)(g_blob + OFF_OVF);

    int   ps[4] = {p4.x, p4.y, p4.z, p4.w};
    int   ts[4] = {q4.x * Rr + r4.x, q4.y * Rr + r4.y,
                   q4.z * Rr + r4.z, q4.w * Rr + r4.w};
    float ws[4] = {w4.x, w4.y, w4.z, w4.w};

#pragma unroll
    for (int k = 0; k < 4; k++) {
        int p = ps[k];
        int c = atomicAdd(&cnt[p], 1);
        if (c < SS) {
            g_syn_tgt[p * SS + c] = ts[k];
            g_syn_w[p * SS + c] = ws[k];
        } else {
            int o = atomicAdd(ovf_cnt, 1);
            if (o < OVF_CAP) {
                g_ovf_pre[o] = p;
                g_ovf_tgt[o] = ts[k];
                g_ovf_w[o] = ws[k];
            }
        }
    }
}

// ---------------------------------------------------------------------------
// One timestep. Reads rec[parity], zeroes it, GLIF3 update, writes spikes,
// push-scatters spikes into rec[parity^1].
__global__ void k_step(const float* __restrict__ x_t,
                       float* __restrict__ out,
                       const float* __restrict__ syn_decay,
                       const float* __restrict__ psc_init,
                       int parity) {
    int n = blockIdx.x * blockDim.x + threadIdx.x;
    if (n >= Nn) return;

    const float4 sd = *(const float4*)syn_decay;
    const float4 pi = *(const float4*)psc_init;

    float* rec_cur = g_blob + OFF_REC + parity * NRr;
    float* rec_nxt = g_blob + OFF_REC + (parity ^ 1) * NRr;
    float* pscp = g_blob + OFF_PSC;
    float* prp  = g_blob + OFF_PR;
    float2* ascp = (float2*)(g_blob + OFF_ASC);

    float4 rec = __ldcg((const float4*)(rec_cur + 4 * n));
    __stcg((float4*)(rec_cur + 4 * n), make_float4(0.f, 0.f, 0.f, 0.f));

    float4 x   = __ldg((const float4*)x_t + n);
    float4 psc = *(float4*)(&pscp[4 * n]);
    float4 pr  = *(float4*)(&prp[4 * n]);
    float4 st  = g_state[n];        // v, r, z
    float2 a   = ascp[n];
    float4 pA  = g_pA[n];           // vth, rst, tref, decay
    float4 pB  = g_pB[n];           // cf, el, amp0, amp1
    float2 pC  = g_pC[n];           // ascd

    float in0 = rec.x + x.x;
    float in1 = rec.y + x.y;
    float in2 = rec.z + x.z;
    float in3 = rec.w + x.w;

    float4 npr, npsc;
    npr.x = pr.x * sd.x + in0 * pi.x;
    npr.y = pr.y * sd.y + in1 * pi.y;
    npr.z = pr.z * sd.z + in2 * pi.z;
    npr.w = pr.w * sd.w + in3 * pi.w;
    npsc.x = psc.x * sd.x + sd.x * pr.x;
    npsc.y = psc.y * sd.y + sd.y * pr.y;
    npsc.z = psc.z * sd.z + sd.z * pr.z;
    npsc.w = psc.w * sd.w + sd.w * pr.w;

    *(float4*)(&pscp[4 * n]) = npsc;
    *(float4*)(&prp[4 * n]) = npr;

    float psum = ((npsc.x + npsc.y) + npsc.z) + npsc.w;
    float z = st.z;
    float input_current = psum + (a.x + a.y);   // OLD asc

    a.x = pC.x * a.x + z * pB.z;
    a.y = pC.y * a.y + z * pB.w;
    ascp[n] = a;

    float nv = pA.w * st.x + pB.x * (input_current + pB.y) + z * pA.y;
    float vsc = (nv - pA.x) / pA.x;

    float zn = (vsc > 0.f) ? 1.f : 0.f;
    if (st.y > 0.f) zn = 0.f;
    float rn = fmaxf(st.y - 1.f + zn * pA.z, 0.f);

    g_state[n] = make_float4(nv, rn, zn, 0.f);
    out[n] = zn;

    if (zn != 0.f) {
        int* cnt = (int*)(g_blob + OFF_CNT);
        int c = cnt[n];
        int m = (c < SS) ? c : SS;
        int base = n * SS;
        for (int s = 0; s < m; s++) {
            atomicAdd(&rec_nxt[g_syn_tgt[base + s]], g_syn_w[base + s]);
        }
        if (c > SS) {  // overflow entries for this neuron (practically never)
            int oc = *(int*)(g_blob + OFF_OVF);
            if (oc > OVF_CAP) oc = OVF_CAP;
            for (int o = 0; o < oc; o++) {
                if (g_ovf_pre[o] == n) {
                    atomicAdd(&rec_nxt[g_ovf_tgt[o]], g_ovf_w[o]);
                }
            }
        }
    }
}

// ---------------------------------------------------------------------------
extern "C" void kernel_launch(void* const* d_in, const int* in_sizes, int n_in,
                              void* d_out, int out_size) {
    const float* w_rec     = (const float*)d_in[0];
    const float* x_ext     = (const float*)d_in[1];
    const float* v0        = (const float*)d_in[2];
    const float* vth       = (const float*)d_in[3];
    const float* vreset    = (const float*)d_in[4];
    const float* tref      = (const float*)d_in[5];
    const float* decay     = (const float*)d_in[6];
    const float* cf        = (const float*)d_in[7];
    const float* el        = (const float*)d_in[8];
    const float* amps      = (const float*)d_in[9];
    const float* ascd      = (const float*)d_in[10];
    const float* syn_decay = (const float*)d_in[11];
    const float* psc_init  = (const float*)d_in[12];
    const int*   pre       = (const int*)d_in[13];
    const int*   post      = (const int*)d_in[14];
    const int*   rcp       = (const int*)d_in[15];
    float* out = (float*)d_out;

    k_prep<<<1856, 256>>>(v0, vth, vreset, tref, decay, cf, el, amps, ascd);
    k_fill<<<(Ee / 4 + 255) / 256, 256>>>(pre, post, rcp, w_rec);

    for (int t = 0; t < Tt; t++) {
        k_step<<<(Nn + 255) / 256, 256>>>(
            x_ext + (size_t)t * NRr,
            out + (size_t)t * Nn,
            syn_decay, psc_init, t & 1);
    }
}